// round 6
// baseline (speedup 1.0000x reference)
#include <cuda_runtime.h>
#include <math.h>

// RotationPerturbationLayer: dense [B,N,N] tent matmul == 4-tap bilinear
// gather with zero-fill. Overhead-dominated tiny kernel. v4: 2D thread
// block (80,4) eliminates ALL index arithmetic (no div/mod), 80 blocks of
// 320 threads (10 warps TLP), warp lanes span x for coalesced gathers.

#define RP_H 80
#define RP_W 80
#define RP_C 3
#define RP_B 4
#define RP_N (RP_H * RP_W)

__global__ void __launch_bounds__(320)
rotation_bilinear_v4(const float* __restrict__ theta,
                     const float* __restrict__ image,
                     float* __restrict__ out)
{
    const int b  = blockIdx.y;
    const int gx = threadIdx.x;                      // [0,80)
    const int gy = blockIdx.x * 4 + threadIdx.y;     // [0,80), exact

    const float cx = (RP_W - 1) * 0.5f;
    const float cy = (RP_H - 1) * 0.5f;

    const float th = __ldg(theta + b) * 0.017453292519943295f;
    float s, c;
    __sincosf(th, &s, &c);   // 2x MUFU

    const float xr = (float)gx - cx;
    const float yr = (float)gy - cy;
    const float sx = fmaf(c, xr, fmaf(s, yr, cx));
    const float sy = fmaf(-s, xr, fmaf(c, yr, cy));

    const int x0 = __float2int_rd(sx);
    const int y0 = __float2int_rd(sy);
    const float fx = sx - (float)x0;
    const float fy = sy - (float)y0;
    const int x1 = x0 + 1;
    const int y1 = y0 + 1;

    const float wx0 = (x0 >= 0 && x0 < RP_W) ? (1.0f - fx) : 0.0f;
    const float wx1 = (x1 >= 0 && x1 < RP_W) ? fx          : 0.0f;
    const float wy0 = (y0 >= 0 && y0 < RP_H) ? (1.0f - fy) : 0.0f;
    const float wy1 = (y1 >= 0 && y1 < RP_H) ? fy          : 0.0f;

    const float w00 = wy0 * wx0;
    const float w01 = wy0 * wx1;
    const float w10 = wy1 * wx0;
    const float w11 = wy1 * wx1;

    const int cx0 = min(max(x0, 0), RP_W - 1);
    const int cx1 = min(max(x1, 0), RP_W - 1);
    const int cy0 = min(max(y0, 0), RP_H - 1);
    const int cy1 = min(max(y1, 0), RP_H - 1);

    const int r0 = cy0 * RP_W;
    const int r1 = cy1 * RP_W;
    const int o00 = r0 + cx0;
    const int o01 = r0 + cx1;
    const int o10 = r1 + cx0;
    const int o11 = r1 + cx1;

    float* op = out + b * (RP_C * RP_N) + gy * RP_W + gx;
    #pragma unroll
    for (int ch = 0; ch < RP_C; ch++) {
        const float* img = image + ch * RP_N;
        float v = w00 * __ldg(img + o00);
        v = fmaf(w01, __ldg(img + o01), v);
        v = fmaf(w10, __ldg(img + o10), v);
        v = fmaf(w11, __ldg(img + o11), v);
        op[ch * RP_N] = v;
    }
}

extern "C" void kernel_launch(void* const* d_in, const int* in_sizes, int n_in,
                              void* d_out, int out_size)
{
    const float* theta = (const float*)d_in[0];  // [4]
    const float* image = (const float*)d_in[1];  // [3,80,80]
    float* out = (float*)d_out;                  // [4,3,80,80]

    dim3 block(80, 4);          // 320 threads, 10 warps
    dim3 grid(RP_H / 4, RP_B);  // (20, 4) = 80 blocks, single wave
    rotation_bilinear_v4<<<grid, block>>>(theta, image, out);
}

// round 7
// speedup vs baseline: 1.1077x; 1.1077x over previous
#include <cuda_runtime.h>
#include <math.h>

// RotationPerturbationLayer: dense [B,N,N] tent matmul == 4-tap bilinear
// gather with zero-fill. Overhead-dominated. v5 = best config (v3: 256thr
// x 100 blocks) + explicit 12-load front-batch so the L2 gather latency is
// paid once (single MLP burst), not per-channel.

#define RP_H 80
#define RP_W 80
#define RP_C 3
#define RP_B 4
#define RP_N (RP_H * RP_W)

__global__ void __launch_bounds__(256)
rotation_bilinear_v5(const float* __restrict__ theta,
                     const float* __restrict__ image,
                     float* __restrict__ out)
{
    const int b = blockIdx.y;
    const int n = blockIdx.x * 256 + threadIdx.x;  // [0, 6400), exact grid
    const int gy = n / RP_W;                        // mul-shift
    const int gx = n - gy * RP_W;

    const float cx = (RP_W - 1) * 0.5f;
    const float cy = (RP_H - 1) * 0.5f;

    const float th = __ldg(theta + b) * 0.017453292519943295f;
    float s, c;
    __sincosf(th, &s, &c);   // 2x MUFU

    const float xr = (float)gx - cx;
    const float yr = (float)gy - cy;
    const float sx = fmaf(c, xr, fmaf(s, yr, cx));
    const float sy = fmaf(-s, xr, fmaf(c, yr, cy));

    const int x0 = __float2int_rd(sx);
    const int y0 = __float2int_rd(sy);
    const float fx = sx - (float)x0;
    const float fy = sy - (float)y0;
    const int x1 = x0 + 1;
    const int y1 = y0 + 1;

    const float wx0 = (x0 >= 0 && x0 < RP_W) ? (1.0f - fx) : 0.0f;
    const float wx1 = (x1 >= 0 && x1 < RP_W) ? fx          : 0.0f;
    const float wy0 = (y0 >= 0 && y0 < RP_H) ? (1.0f - fy) : 0.0f;
    const float wy1 = (y1 >= 0 && y1 < RP_H) ? fy          : 0.0f;

    const float w00 = wy0 * wx0;
    const float w01 = wy0 * wx1;
    const float w10 = wy1 * wx0;
    const float w11 = wy1 * wx1;

    const int cx0 = min(max(x0, 0), RP_W - 1);
    const int cx1 = min(max(x1, 0), RP_W - 1);
    const int cy0 = min(max(y0, 0), RP_H - 1);
    const int cy1 = min(max(y1, 0), RP_H - 1);

    const int r0 = cy0 * RP_W;
    const int r1 = cy1 * RP_W;
    const int o00 = r0 + cx0;
    const int o01 = r0 + cx1;
    const int o10 = r1 + cx0;
    const int o11 = r1 + cx1;

    // Front-batch ALL 12 gathers into one MLP burst (pay L2 latency once).
    float t[RP_C][4];
    #pragma unroll
    for (int ch = 0; ch < RP_C; ch++) {
        const float* img = image + ch * RP_N;
        t[ch][0] = __ldg(img + o00);
        t[ch][1] = __ldg(img + o01);
        t[ch][2] = __ldg(img + o10);
        t[ch][3] = __ldg(img + o11);
    }

    float* op = out + b * (RP_C * RP_N) + n;
    #pragma unroll
    for (int ch = 0; ch < RP_C; ch++) {
        float v = w00 * t[ch][0];
        v = fmaf(w01, t[ch][1], v);
        v = fmaf(w10, t[ch][2], v);
        v = fmaf(w11, t[ch][3], v);
        op[ch * RP_N] = v;
    }
}

extern "C" void kernel_launch(void* const* d_in, const int* in_sizes, int n_in,
                              void* d_out, int out_size)
{
    const float* theta = (const float*)d_in[0];  // [4]
    const float* image = (const float*)d_in[1];  // [3,80,80]
    float* out = (float*)d_out;                  // [4,3,80,80]

    dim3 grid(RP_N / 256, RP_B);  // (25, 4) -> 100 blocks x 256 threads
    rotation_bilinear_v5<<<grid, 256>>>(theta, image, out);
}